// round 8
// baseline (speedup 1.0000x reference)
#include <cuda_runtime.h>
#include <cuda_bf16.h>
#include <cstdint>

#define B_ROWS 2048
#define D_DIM  512
#define N_COLS 100000            // = 3125 * 32 exactly
#define NPAD   100096            // 782*128
#define NW     (NPAD / 32)       // 3128
#define F_LEN  64
#define QSCALE 25.4f             // 127/5

#define BM 128
#define BN 128
#define BKB 128                  // k-bytes (int8 elems) per chunk
#define KT (D_DIM / BKB)         // 4 chunks
#define NSTAGE 3
#define ST 144                   // smem row stride bytes (conflict-free)
#define A_ST (BM * ST)           // 18432
#define B_ST (BN * ST)           // 18432
#define STG (A_ST + B_ST)        // 36864
#define SMEM_DYN (NSTAGE * STG)  // 110592 -> 2 CTAs/SM

// ---------------- device scratch ----------------
__device__ __align__(128) signed char g_ri8T[(size_t)NPAD * D_DIM];  // [n][k] int8, 51MB
__device__ __align__(128) signed char g_qi8[B_ROWS * D_DIM];         // [m][k] int8
__device__ float    g_tgtf[B_ROWS];   // exact fp32 target scaled by QSCALE^2
__device__ int      g_counts[B_ROWS];
__device__ unsigned g_mask[(size_t)B_ROWS * NW];
__device__ int      g_is64;

// ---------------- helpers ----------------
__device__ __forceinline__ uint32_t smem_u32(const void* p) {
    uint32_t a;
    asm("{ .reg .u64 t; cvta.to.shared.u64 t, %1; cvt.u32.u64 %0, t; }" : "=r"(a) : "l"(p));
    return a;
}
__device__ __forceinline__ void cpasync16(uint32_t dst, const void* src) {
    asm volatile("cp.async.cg.shared.global [%0],[%1],16;" :: "r"(dst), "l"(src));
}
__device__ __forceinline__ signed char quant(float v) {
    int x = __float2int_rn(v * QSCALE);
    x = max(-127, min(127, x));
    return (signed char)x;
}
__device__ __forceinline__ int load_idx(const void* p, int i) {
    if (g_is64) return (int)((const long long*)p)[i];
    return ((const int*)p)[i];
}

// ---------------- [0] fused prep: mask init + q quant + counts + detect ----------------
__global__ void k_prep0(const float* __restrict__ q, const unsigned* __restrict__ qb) {
    int idx = blockIdx.x * 256 + threadIdx.x;              // B_ROWS*NW threads
    int w = idx % NW;
    g_mask[idx] = (w >= (N_COLS / 32)) ? 0xFFFFFFFFu : 0u;
    if (idx < B_ROWS * D_DIM) g_qi8[idx] = quant(q[idx]);
    if (idx < B_ROWS) g_counts[idx] = 0;
    if (blockIdx.x == 0) {                                 // index dtype detect
        __shared__ unsigned s;
        if (threadIdx.x == 0) s = 0;
        __syncthreads();
        unsigned a = 0;
        for (int i = threadIdx.x; i < 3 * B_ROWS; i += 256) a |= qb[2 * i + 1];
        atomicOr(&s, a);
        __syncthreads();
        if (threadIdx.x == 0) g_is64 = (s == 0) ? 1 : 0;
    }
}

// ---------------- [1] transpose + quantize rhs fp32[D][N] -> int8 [NPAD][D] ----------------
__global__ void k_prep_rhsT(const float* __restrict__ rhs) {
    __shared__ float t[32][33];
    const int nb = blockIdx.x * 32, db = blockIdx.y * 32;
    const int tx = threadIdx.x, ty = threadIdx.y;
    const int n_in = nb + tx;
#pragma unroll
    for (int j = 0; j < 4; j++) {
        int d = db + ty + j * 8;
        t[ty + j * 8][tx] = (n_in < N_COLS) ? rhs[(size_t)d * N_COLS + n_in] : 0.f;
    }
    __syncthreads();
    const int tid = ty * 32 + tx;
    const int nl = tid >> 3, c4 = tid & 7;                 // n-row, 4-byte group
    uchar4 pk;
    pk.x = (unsigned char)quant(t[c4 * 4 + 0][nl]);
    pk.y = (unsigned char)quant(t[c4 * 4 + 1][nl]);
    pk.z = (unsigned char)quant(t[c4 * 4 + 2][nl]);
    pk.w = (unsigned char)quant(t[c4 * 4 + 3][nl]);
    *reinterpret_cast<uchar4*>(&g_ri8T[(size_t)(nb + nl) * D_DIM + db + c4 * 4]) = pk;
}

// ---------------- [2] fused mask scatter + EXACT fp32 targets (scaled to int domain) ----
__global__ void k_row(const float* __restrict__ q, const float* __restrict__ rhs,
                      const void* __restrict__ queries, const void* __restrict__ filt) {
    const int b = blockIdx.x, tid = threadIdx.x;
    if (tid >= 32 && tid <= 96) {                          // mask scatter: 65 indices
        int j = tid - 32;
        int idx = (j < F_LEN) ? load_idx(filt, b * F_LEN + j) : load_idx(queries, b * 3 + 2);
        atomicOr(&g_mask[(size_t)b * NW + (idx >> 5)], 1u << (idx & 31));
    }
    if (tid < 32) {                                        // exact fp32 target, common-mode free
        int tru = load_idx(queries, b * 3 + 2);
        float s = 0.f;
        for (int d = tid; d < D_DIM; d += 32)
            s += q[b * D_DIM + d] * rhs[(size_t)d * N_COLS + tru];
#pragma unroll
        for (int o = 16; o > 0; o >>= 1) s += __shfl_xor_sync(0xffffffffu, s, o);
        if (tid == 0) g_tgtf[b] = s * (QSCALE * QSCALE);
    }
}

// ---------------- [3] int8 IMMA GEMM + counting epilogue ----------------
__global__ void __launch_bounds__(256, 2) k_gemm() {
    extern __shared__ char smem[];
    const uint32_t sbase = smem_u32(smem);
    const int tid = threadIdx.x, lane = tid & 31, warp = tid >> 5;
    const int wm = warp >> 1, wn = warp & 1;               // 4x2 warps, 32x64 tiles
    const int m0 = blockIdx.x * BM, n0 = blockIdx.y * BN;

    int acc[2][8][4];
#pragma unroll
    for (int mi = 0; mi < 2; mi++)
#pragma unroll
        for (int ni = 0; ni < 8; ni++)
#pragma unroll
            for (int e = 0; e < 4; e++) acc[mi][ni][e] = 0;

    auto load_stage = [&](int kt, int buf) {
        const int k0 = kt * BKB;
        const uint32_t aB = sbase + buf * STG;
        const uint32_t bB = aB + A_ST;
#pragma unroll
        for (int i = 0; i < 4; i++) {                      // A: 1024 x 16B
            int c = tid + i * 256, r = c >> 3, cc = c & 7;
            cpasync16(aB + (uint32_t)(r * ST + cc * 16),
                      &g_qi8[(size_t)(m0 + r) * D_DIM + k0 + cc * 16]);
        }
#pragma unroll
        for (int i = 0; i < 4; i++) {                      // B: 1024 x 16B
            int c = tid + i * 256, r = c >> 3, cc = c & 7;
            cpasync16(bB + (uint32_t)(r * ST + cc * 16),
                      &g_ri8T[(size_t)(n0 + r) * D_DIM + k0 + cc * 16]);
        }
        asm volatile("cp.async.commit_group;");
    };

    auto compute = [&](int buf) {
        const uint32_t aB = sbase + buf * STG;
        const uint32_t bB = aB + A_ST;
#pragma unroll
        for (int ks = 0; ks < 4; ks++) {                   // 4 k-steps of 32 int8
            uint32_t af[2][4];
#pragma unroll
            for (int mi = 0; mi < 2; mi++) {
                uint32_t a = aB + (uint32_t)((wm * 32 + mi * 16 + (lane & 15)) * ST
                                             + ks * 32 + (lane >> 4) * 16);
                asm volatile("ldmatrix.sync.aligned.m8n8.x4.shared.b16 {%0,%1,%2,%3},[%4];"
                             : "=r"(af[mi][0]), "=r"(af[mi][1]), "=r"(af[mi][2]), "=r"(af[mi][3])
                             : "r"(a));
            }
            uint32_t bfm[8][2];
#pragma unroll
            for (int nj = 0; nj < 4; nj++) {               // pairs of n8 tiles
                uint32_t a = bB + (uint32_t)((wn * 64 + nj * 16 + (lane & 7) + ((lane >> 4) & 1) * 8) * ST
                                             + ks * 32 + ((lane >> 3) & 1) * 16);
                uint32_t r0, r1, r2, r3;
                asm volatile("ldmatrix.sync.aligned.m8n8.x4.shared.b16 {%0,%1,%2,%3},[%4];"
                             : "=r"(r0), "=r"(r1), "=r"(r2), "=r"(r3) : "r"(a));
                bfm[nj * 2][0] = r0;     bfm[nj * 2][1] = r1;
                bfm[nj * 2 + 1][0] = r2; bfm[nj * 2 + 1][1] = r3;
            }
#pragma unroll
            for (int mi = 0; mi < 2; mi++)
#pragma unroll
                for (int ni = 0; ni < 8; ni++)
                    asm volatile("mma.sync.aligned.m16n8k32.row.col.s32.s8.s8.s32 "
                                 "{%0,%1,%2,%3},{%4,%5,%6,%7},{%8,%9},{%0,%1,%2,%3};"
                                 : "+r"(acc[mi][ni][0]), "+r"(acc[mi][ni][1]),
                                   "+r"(acc[mi][ni][2]), "+r"(acc[mi][ni][3])
                                 : "r"(af[mi][0]), "r"(af[mi][1]), "r"(af[mi][2]), "r"(af[mi][3]),
                                   "r"(bfm[ni][0]), "r"(bfm[ni][1]));
        }
    };

    load_stage(0, 0);
    load_stage(1, 1);
#pragma unroll 1
    for (int kt = 0; kt < KT; kt++) {
        asm volatile("cp.async.wait_group %0;" :: "n"(1));
        __syncthreads();
        compute(kt % NSTAGE);
        __syncthreads();
        if (kt + 2 < KT) load_stage(kt + 2, (kt + 2) % NSTAGE);
        else asm volatile("cp.async.commit_group;");       // keep group count in step
    }

    // ---- counting epilogue: float compare vs exact scaled target (exact: |acc|<2^24) ----
    const int m_base = m0 + wm * 32;
    const int n_base = n0 + wn * 64;
    const int r_in = lane >> 2;
    const int c_in = (lane & 3) * 2;
    const int wb = n_base >> 5;

#pragma unroll
    for (int mi = 0; mi < 2; mi++) {
        int r0 = m_base + mi * 16 + r_in;
        int r1 = r0 + 8;
        float t0 = g_tgtf[r0], t1 = g_tgtf[r1];
        unsigned k00 = ~g_mask[(size_t)r0 * NW + wb];
        unsigned k01 = ~g_mask[(size_t)r0 * NW + wb + 1];
        unsigned k10 = ~g_mask[(size_t)r1 * NW + wb];
        unsigned k11 = ~g_mask[(size_t)r1 * NW + wb + 1];
        int c0 = 0, c1 = 0;
#pragma unroll
        for (int ni = 0; ni < 8; ni++) {
#pragma unroll
            for (int e = 0; e < 2; e++) {
                int p = ni * 8 + c_in + e;
                unsigned kw0 = (p < 32) ? k00 : k01;
                unsigned kw1 = (p < 32) ? k10 : k11;
                c0 += (int)((kw0 >> (p & 31)) & 1u) & (int)((float)acc[mi][ni][e]     >= t0);
                c1 += (int)((kw1 >> (p & 31)) & 1u) & (int)((float)acc[mi][ni][2 + e] >= t1);
            }
        }
        c0 += __shfl_xor_sync(0xffffffffu, c0, 1);
        c0 += __shfl_xor_sync(0xffffffffu, c0, 2);
        c1 += __shfl_xor_sync(0xffffffffu, c1, 1);
        c1 += __shfl_xor_sync(0xffffffffu, c1, 2);
        if ((lane & 3) == 0) {
            atomicAdd(&g_counts[r0], c0);
            atomicAdd(&g_counts[r1], c1);
        }
    }
}

// ---------------- [4] finalize ----------------
__global__ void k_final(float* __restrict__ out) {
    int i = blockIdx.x * 256 + threadIdx.x;
    if (i < B_ROWS) out[i] = 1.0f + (float)g_counts[i];
}

// ---------------- launch ----------------
extern "C" void kernel_launch(void* const* d_in, const int* in_sizes, int n_in,
                              void* d_out, int out_size) {
    const float* q   = (const float*)d_in[0];
    const float* rhs = (const float*)d_in[1];
    const void*  queries = d_in[2];
    const void*  filt    = d_in[3];
    float* out = (float*)d_out;

    cudaFuncSetAttribute(k_gemm, cudaFuncAttributeMaxDynamicSharedMemorySize, SMEM_DYN);

    k_prep0<<<(B_ROWS * NW) / 256, 256>>>(q, (const unsigned*)queries);
    k_prep_rhsT<<<dim3(NPAD / 32, D_DIM / 32), dim3(32, 8)>>>(rhs);
    k_row<<<B_ROWS, 128>>>(q, rhs, queries, filt);
    k_gemm<<<dim3(B_ROWS / BM, NPAD / BN), 256, SMEM_DYN>>>();
    k_final<<<(B_ROWS + 255) / 256, 256>>>(out);
}

// round 9
// speedup vs baseline: 1.9875x; 1.9875x over previous
#include <cuda_runtime.h>
#include <cuda_bf16.h>
#include <cstdint>

#define B_ROWS 2048
#define D_DIM  512
#define N_COLS 100000            // = 3125 * 32 exactly
#define NPAD   100096            // 782*128
#define NW     (NPAD / 32)       // 3128
#define F_LEN  64

#define BM 128
#define BN 128
#define BK 32
#define KT (D_DIM / BK)          // 16 chunks
#define NSTAGE 4
#define SA_STRIDE 40             // bf16 elems; 80B rows, conflict-free ldmatrix
#define SB_STRIDE 136            // bf16 elems; 272B rows
#define SA_B (BM * SA_STRIDE * 2)              // 10240
#define SB_B (BK * SB_STRIDE * 2)              // 8704
#define STG  (SA_B + SB_B)                     // 18944
#define SMEM_DYN (NSTAGE * STG)                // 75776 -> 2 CTAs/SM

// ---------------- device scratch ----------------
__device__ __align__(128) __nv_bfloat16 g_rhs_bf16[(size_t)D_DIM * NPAD];  // [d][n] padded
__device__ __align__(128) __nv_bfloat16 g_q_bf16[B_ROWS * D_DIM];          // [m][k]
__device__ float    g_targets[B_ROWS];
__device__ int      g_counts[B_ROWS];
__device__ unsigned g_mask[(size_t)B_ROWS * NW];
__device__ int      g_is64;

// ---------------- helpers ----------------
__device__ __forceinline__ uint32_t smem_u32(const void* p) {
    uint32_t a;
    asm("{ .reg .u64 t; cvta.to.shared.u64 t, %1; cvt.u32.u64 %0, t; }" : "=r"(a) : "l"(p));
    return a;
}
__device__ __forceinline__ void cpasync16(uint32_t dst, const void* src) {
    asm volatile("cp.async.cg.shared.global [%0],[%1],16;" :: "r"(dst), "l"(src));
}
__device__ __forceinline__ int load_idx(const void* p, int i) {
    if (g_is64) return (int)((const long long*)p)[i];
    return ((const int*)p)[i];
}

// ---------------- [0] fused prep: mask init + q->bf16 + counts + dtype detect ----------------
__global__ void k_prep0(const float* __restrict__ q, const unsigned* __restrict__ qb) {
    int idx = blockIdx.x * 256 + threadIdx.x;              // B_ROWS*NW threads
    int w = idx % NW;
    g_mask[idx] = (w >= (N_COLS / 32)) ? 0xFFFFFFFFu : 0u;
    if (idx < B_ROWS * D_DIM) g_q_bf16[idx] = __float2bfloat16(q[idx]);
    if (idx < B_ROWS) g_counts[idx] = 0;
    if (blockIdx.x == 0) {
        __shared__ unsigned s;
        if (threadIdx.x == 0) s = 0;
        __syncthreads();
        unsigned a = 0;
        for (int i = threadIdx.x; i < 3 * B_ROWS; i += 256) a |= qb[2 * i + 1];
        atomicOr(&s, a);
        __syncthreads();
        if (threadIdx.x == 0) g_is64 = (s == 0) ? 1 : 0;
    }
}

// ---------------- [1] rhs fp32 -> bf16 padded ----------------
__global__ void k_prep_rhs(const float* __restrict__ rhs) {
    int idx = blockIdx.x * 256 + threadIdx.x;              // D_DIM*NPAD threads
    int d = idx / NPAD, n = idx - d * NPAD;
    float v = (n < N_COLS) ? rhs[(size_t)d * N_COLS + n] : 0.f;
    g_rhs_bf16[idx] = __float2bfloat16(v);
}

// ---------------- [2] fused mask scatter + exact fp32 targets ----------------
__global__ void k_row(const float* __restrict__ q, const float* __restrict__ rhs,
                      const void* __restrict__ queries, const void* __restrict__ filt) {
    const int b = blockIdx.x, tid = threadIdx.x;
    if (tid >= 32 && tid <= 96) {                          // 65 masked indices
        int j = tid - 32;
        int idx = (j < F_LEN) ? load_idx(filt, b * F_LEN + j) : load_idx(queries, b * 3 + 2);
        atomicOr(&g_mask[(size_t)b * NW + (idx >> 5)], 1u << (idx & 31));
    }
    if (tid < 32) {                                        // exact fp32 target
        int tru = load_idx(queries, b * 3 + 2);
        float s = 0.f;
        for (int d = tid; d < D_DIM; d += 32)
            s += q[b * D_DIM + d] * rhs[(size_t)d * N_COLS + tru];
#pragma unroll
        for (int o = 16; o > 0; o >>= 1) s += __shfl_xor_sync(0xffffffffu, s, o);
        if (tid == 0) g_targets[b] = s;
    }
}

// ---------------- [3] bf16 MMA GEMM, 4-stage cp.async, 1 sync/chunk ----------------
__global__ void __launch_bounds__(256, 2) k_gemm() {
    extern __shared__ char smem[];
    const uint32_t sbase = smem_u32(smem);
    const int tid = threadIdx.x, lane = tid & 31, warp = tid >> 5;
    const int wm = warp >> 1, wn = warp & 1;               // 4x2 warps, 32x64 tiles
    const int m0 = blockIdx.x * BM, n0 = blockIdx.y * BN;

    float acc[2][8][4];
#pragma unroll
    for (int mi = 0; mi < 2; mi++)
#pragma unroll
        for (int ni = 0; ni < 8; ni++)
#pragma unroll
            for (int e = 0; e < 4; e++) acc[mi][ni][e] = 0.f;

    auto load_stage = [&](int kt, int buf) {
        const int k0 = kt * BK;
        const uint32_t aB = sbase + buf * STG;
        const uint32_t bB = aB + SA_B;
#pragma unroll
        for (int i = 0; i < 2; i++) {                      // A: 512 x 16B
            int c = tid + i * 256, r = c >> 2, cc = c & 3;
            cpasync16(aB + (uint32_t)(r * SA_STRIDE + cc * 8) * 2,
                      &g_q_bf16[(size_t)(m0 + r) * D_DIM + k0 + cc * 8]);
        }
#pragma unroll
        for (int i = 0; i < 2; i++) {                      // B: 512 x 16B
            int c = tid + i * 256, r = c >> 4, cc = c & 15;
            cpasync16(bB + (uint32_t)(r * SB_STRIDE + cc * 8) * 2,
                      &g_rhs_bf16[(size_t)(k0 + r) * NPAD + n0 + cc * 8]);
        }
        asm volatile("cp.async.commit_group;");
    };

    auto compute = [&](int buf) {
        const uint32_t aB = sbase + buf * STG;
        const uint32_t bB = aB + SA_B;
#pragma unroll
        for (int ks = 0; ks < BK; ks += 16) {
            uint32_t af[2][4];
#pragma unroll
            for (int mi = 0; mi < 2; mi++) {
                uint32_t a = aB + (uint32_t)((wm * 32 + mi * 16 + (lane & 15)) * SA_STRIDE
                                             + ks + (lane >> 4) * 8) * 2;
                asm volatile("ldmatrix.sync.aligned.m8n8.x4.shared.b16 {%0,%1,%2,%3},[%4];"
                             : "=r"(af[mi][0]), "=r"(af[mi][1]), "=r"(af[mi][2]), "=r"(af[mi][3])
                             : "r"(a));
            }
            uint32_t bfm[8][2];
#pragma unroll
            for (int nj = 0; nj < 4; nj++) {
                uint32_t a = bB + (uint32_t)((ks + (lane & 15)) * SB_STRIDE
                                             + wn * 64 + nj * 16 + (lane >> 4) * 8) * 2;
                uint32_t r0, r1, r2, r3;
                asm volatile("ldmatrix.sync.aligned.m8n8.x4.trans.shared.b16 {%0,%1,%2,%3},[%4];"
                             : "=r"(r0), "=r"(r1), "=r"(r2), "=r"(r3) : "r"(a));
                bfm[nj * 2][0] = r0;     bfm[nj * 2][1] = r1;
                bfm[nj * 2 + 1][0] = r2; bfm[nj * 2 + 1][1] = r3;
            }
#pragma unroll
            for (int mi = 0; mi < 2; mi++)
#pragma unroll
                for (int ni = 0; ni < 8; ni++)
                    asm volatile("mma.sync.aligned.m16n8k16.row.col.f32.bf16.bf16.f32 "
                                 "{%0,%1,%2,%3},{%4,%5,%6,%7},{%8,%9},{%0,%1,%2,%3};"
                                 : "+f"(acc[mi][ni][0]), "+f"(acc[mi][ni][1]),
                                   "+f"(acc[mi][ni][2]), "+f"(acc[mi][ni][3])
                                 : "r"(af[mi][0]), "r"(af[mi][1]), "r"(af[mi][2]), "r"(af[mi][3]),
                                   "r"(bfm[ni][0]), "r"(bfm[ni][1]));
        }
    };

    load_stage(0, 0);
    load_stage(1, 1);
    load_stage(2, 2);
#pragma unroll 1
    for (int kt = 0; kt < KT; kt++) {
        if (kt < KT - 2)      asm volatile("cp.async.wait_group 2;");
        else if (kt == KT - 2) asm volatile("cp.async.wait_group 1;");
        else                  asm volatile("cp.async.wait_group 0;");
        __syncthreads();      // stage kt loaded everywhere; compute(kt-1) done on all warps
        compute(kt & 3);
        if (kt + 3 < KT) load_stage(kt + 3, (kt + 3) & 3);
    }

    // ---- counting epilogue (pads pre-masked; no bounds check) ----
    const int m_base = m0 + wm * 32;
    const int n_base = n0 + wn * 64;
    const int r_in = lane >> 2;
    const int c_in = (lane & 3) * 2;
    const int wb = n_base >> 5;

#pragma unroll
    for (int mi = 0; mi < 2; mi++) {
        int r0 = m_base + mi * 16 + r_in;
        int r1 = r0 + 8;
        float t0 = g_targets[r0], t1 = g_targets[r1];
        unsigned k00 = ~g_mask[(size_t)r0 * NW + wb];
        unsigned k01 = ~g_mask[(size_t)r0 * NW + wb + 1];
        unsigned k10 = ~g_mask[(size_t)r1 * NW + wb];
        unsigned k11 = ~g_mask[(size_t)r1 * NW + wb + 1];
        int c0 = 0, c1 = 0;
#pragma unroll
        for (int ni = 0; ni < 8; ni++) {
#pragma unroll
            for (int e = 0; e < 2; e++) {
                int p = ni * 8 + c_in + e;
                unsigned kw0 = (p < 32) ? k00 : k01;
                unsigned kw1 = (p < 32) ? k10 : k11;
                c0 += (int)((kw0 >> (p & 31)) & 1u) & (int)(acc[mi][ni][e]     >= t0);
                c1 += (int)((kw1 >> (p & 31)) & 1u) & (int)(acc[mi][ni][2 + e] >= t1);
            }
        }
        c0 += __shfl_xor_sync(0xffffffffu, c0, 1);
        c0 += __shfl_xor_sync(0xffffffffu, c0, 2);
        c1 += __shfl_xor_sync(0xffffffffu, c1, 1);
        c1 += __shfl_xor_sync(0xffffffffu, c1, 2);
        if ((lane & 3) == 0) {
            atomicAdd(&g_counts[r0], c0);
            atomicAdd(&g_counts[r1], c1);
        }
    }
}

// ---------------- [4] finalize ----------------
__global__ void k_final(float* __restrict__ out) {
    int i = blockIdx.x * 256 + threadIdx.x;
    if (i < B_ROWS) out[i] = 1.0f + (float)g_counts[i];
}

// ---------------- launch ----------------
extern "C" void kernel_launch(void* const* d_in, const int* in_sizes, int n_in,
                              void* d_out, int out_size) {
    const float* q   = (const float*)d_in[0];
    const float* rhs = (const float*)d_in[1];
    const void*  queries = d_in[2];
    const void*  filt    = d_in[3];
    float* out = (float*)d_out;

    cudaFuncSetAttribute(k_gemm, cudaFuncAttributeMaxDynamicSharedMemorySize, SMEM_DYN);

    k_prep0<<<(B_ROWS * NW) / 256, 256>>>(q, (const unsigned*)queries);
    k_prep_rhs<<<(D_DIM * NPAD) / 256, 256>>>(rhs);
    k_row<<<B_ROWS, 128>>>(q, rhs, queries, filt);
    k_gemm<<<dim3(B_ROWS / BM, NPAD / BN), 256, SMEM_DYN>>>();
    k_final<<<(B_ROWS + 255) / 256, 256>>>(out);
}

// round 10
// speedup vs baseline: 2.1733x; 1.0935x over previous
#include <cuda_runtime.h>
#include <cuda_bf16.h>
#include <cstdint>

#define B_ROWS 2048
#define D_DIM  512
#define N_COLS 100000            // = 3125 * 32 exactly
#define NPAD   100096            // 782*128
#define NW     (NPAD / 32)       // 3128
#define F_LEN  64

#define BM 128
#define BN 128
#define BK 64                    // k elems per chunk
#define KT (D_DIM / BK)          // 8 chunks
#define NSTAGE 3
#define ST 144                   // bytes per row (128B data + 16B pad; 9*16 -> conflict-free)
#define A_ST (BM * ST)           // 18432
#define B_ST (BN * ST)           // 18432
#define STG (A_ST + B_ST)        // 36864
#define SMEM_DYN (NSTAGE * STG)  // 110592 -> 2 CTAs/SM (221KB of 228KB)

// ---------------- device scratch ----------------
__device__ __align__(128) __nv_bfloat16 g_rhs_T[(size_t)NPAD * D_DIM];   // [n][k]
__device__ __align__(128) __nv_bfloat16 g_q_bf16[B_ROWS * D_DIM];        // [m][k]
__device__ float    g_targets[B_ROWS];
__device__ int      g_counts[B_ROWS];
__device__ unsigned g_mask[(size_t)B_ROWS * NW];
__device__ int      g_is64;

// ---------------- helpers ----------------
__device__ __forceinline__ uint32_t smem_u32(const void* p) {
    uint32_t a;
    asm("{ .reg .u64 t; cvta.to.shared.u64 t, %1; cvt.u32.u64 %0, t; }" : "=r"(a) : "l"(p));
    return a;
}
__device__ __forceinline__ void cpasync16(uint32_t dst, const void* src) {
    asm volatile("cp.async.cg.shared.global [%0],[%1],16;" :: "r"(dst), "l"(src));
}
__device__ __forceinline__ int load_idx(const void* p, int i) {
    if (g_is64) return (int)((const long long*)p)[i];
    return ((const int*)p)[i];
}

// ---------------- [0] fused prep: mask init + q->bf16 + counts + dtype detect ----------------
__global__ void k_prep0(const float* __restrict__ q, const unsigned* __restrict__ qb) {
    int idx = blockIdx.x * 256 + threadIdx.x;              // B_ROWS*NW threads
    int w = idx % NW;
    g_mask[idx] = (w >= (N_COLS / 32)) ? 0xFFFFFFFFu : 0u;
    if (idx < B_ROWS * D_DIM) g_q_bf16[idx] = __float2bfloat16(q[idx]);
    if (idx < B_ROWS) g_counts[idx] = 0;
    if (blockIdx.x == 0) {
        __shared__ unsigned s;
        if (threadIdx.x == 0) s = 0;
        __syncthreads();
        unsigned a = 0;
        for (int i = threadIdx.x; i < 3 * B_ROWS; i += 256) a |= qb[2 * i + 1];
        atomicOr(&s, a);
        __syncthreads();
        if (threadIdx.x == 0) g_is64 = (s == 0) ? 1 : 0;
    }
}

// ---------------- [1] transpose rhs fp32[D][N] -> bf16 [NPAD][D] ----------------
__global__ void k_prep_rhsT(const float* __restrict__ rhs) {
    __shared__ float t[32][33];
    const int nb = blockIdx.x * 32, db = blockIdx.y * 32;
    const int tx = threadIdx.x, ty = threadIdx.y;
    const int n_in = nb + tx;
#pragma unroll
    for (int j = 0; j < 4; j++) {
        int d = db + ty + j * 8;
        t[ty + j * 8][tx] = (n_in < N_COLS) ? rhs[(size_t)d * N_COLS + n_in] : 0.f;
    }
    __syncthreads();
    const int tid = ty * 32 + tx;
    const int nl = tid >> 3, c4 = tid & 7;                 // out row n, 4-elem group along d
    __nv_bfloat162 p0, p1;
    p0.x = __float2bfloat16(t[c4 * 4 + 0][nl]);
    p0.y = __float2bfloat16(t[c4 * 4 + 1][nl]);
    p1.x = __float2bfloat16(t[c4 * 4 + 2][nl]);
    p1.y = __float2bfloat16(t[c4 * 4 + 3][nl]);
    __nv_bfloat162* dst = reinterpret_cast<__nv_bfloat162*>(
        &g_rhs_T[(size_t)(nb + nl) * D_DIM + db + c4 * 4]);
    dst[0] = p0;
    dst[1] = p1;
}

// ---------------- [2] fused mask scatter + exact fp32 targets ----------------
__global__ void k_row(const float* __restrict__ q, const float* __restrict__ rhs,
                      const void* __restrict__ queries, const void* __restrict__ filt) {
    const int b = blockIdx.x, tid = threadIdx.x;
    if (tid >= 32 && tid <= 96) {                          // 65 masked indices
        int j = tid - 32;
        int idx = (j < F_LEN) ? load_idx(filt, b * F_LEN + j) : load_idx(queries, b * 3 + 2);
        atomicOr(&g_mask[(size_t)b * NW + (idx >> 5)], 1u << (idx & 31));
    }
    if (tid < 32) {                                        // exact fp32 target
        int tru = load_idx(queries, b * 3 + 2);
        float s = 0.f;
        for (int d = tid; d < D_DIM; d += 32)
            s += q[b * D_DIM + d] * rhs[(size_t)d * N_COLS + tru];
#pragma unroll
        for (int o = 16; o > 0; o >>= 1) s += __shfl_xor_sync(0xffffffffu, s, o);
        if (tid == 0) g_targets[b] = s;
    }
}

// ---------------- [3] bf16 MMA GEMM: BK=64, 3 stages, both operands k-major ----------------
__global__ void __launch_bounds__(256, 2) k_gemm() {
    extern __shared__ char smem[];
    const uint32_t sbase = smem_u32(smem);
    const int tid = threadIdx.x, lane = tid & 31, warp = tid >> 5;
    const int wm = warp >> 1, wn = warp & 1;               // 4x2 warps, 32x64 tiles
    const int m0 = blockIdx.x * BM, n0 = blockIdx.y * BN;

    float acc[2][8][4];
#pragma unroll
    for (int mi = 0; mi < 2; mi++)
#pragma unroll
        for (int ni = 0; ni < 8; ni++)
#pragma unroll
            for (int e = 0; e < 4; e++) acc[mi][ni][e] = 0.f;

    auto load_stage = [&](int kt, int buf) {
        const int k0 = kt * BK;
        const uint32_t aB = sbase + buf * STG;
        const uint32_t bB = aB + A_ST;
#pragma unroll
        for (int i = 0; i < 4; i++) {                      // A: 1024 x 16B
            int c = tid + i * 256, r = c >> 3, cc = c & 7;
            cpasync16(aB + (uint32_t)(r * ST + cc * 16),
                      &g_q_bf16[(size_t)(m0 + r) * D_DIM + k0 + cc * 8]);
        }
#pragma unroll
        for (int i = 0; i < 4; i++) {                      // B: 1024 x 16B
            int c = tid + i * 256, r = c >> 3, cc = c & 7;
            cpasync16(bB + (uint32_t)(r * ST + cc * 16),
                      &g_rhs_T[(size_t)(n0 + r) * D_DIM + k0 + cc * 8]);
        }
        asm volatile("cp.async.commit_group;");
    };

    auto compute = [&](int buf) {
        const uint32_t aB = sbase + buf * STG;
        const uint32_t bB = aB + A_ST;
#pragma unroll
        for (int ks = 0; ks < 4; ks++) {                   // 4 k-steps of 16
            uint32_t af[2][4];
#pragma unroll
            for (int mi = 0; mi < 2; mi++) {
                uint32_t a = aB + (uint32_t)((wm * 32 + mi * 16 + (lane & 15)) * ST
                                             + ks * 32 + (lane >> 4) * 16);
                asm volatile("ldmatrix.sync.aligned.m8n8.x4.shared.b16 {%0,%1,%2,%3},[%4];"
                             : "=r"(af[mi][0]), "=r"(af[mi][1]), "=r"(af[mi][2]), "=r"(af[mi][3])
                             : "r"(a));
            }
            uint32_t bfm[8][2];
#pragma unroll
            for (int nj = 0; nj < 4; nj++) {               // two n8 tiles per ldmatrix.x4
                uint32_t a = bB + (uint32_t)((wn * 64 + nj * 16 + (lane & 7) + ((lane >> 4) & 1) * 8) * ST
                                             + ks * 32 + ((lane >> 3) & 1) * 16);
                uint32_t r0, r1, r2, r3;
                asm volatile("ldmatrix.sync.aligned.m8n8.x4.shared.b16 {%0,%1,%2,%3},[%4];"
                             : "=r"(r0), "=r"(r1), "=r"(r2), "=r"(r3) : "r"(a));
                bfm[nj * 2][0] = r0;     bfm[nj * 2][1] = r1;
                bfm[nj * 2 + 1][0] = r2; bfm[nj * 2 + 1][1] = r3;
            }
#pragma unroll
            for (int mi = 0; mi < 2; mi++)
#pragma unroll
                for (int ni = 0; ni < 8; ni++)
                    asm volatile("mma.sync.aligned.m16n8k16.row.col.f32.bf16.bf16.f32 "
                                 "{%0,%1,%2,%3},{%4,%5,%6,%7},{%8,%9},{%0,%1,%2,%3};"
                                 : "+f"(acc[mi][ni][0]), "+f"(acc[mi][ni][1]),
                                   "+f"(acc[mi][ni][2]), "+f"(acc[mi][ni][3])
                                 : "r"(af[mi][0]), "r"(af[mi][1]), "r"(af[mi][2]), "r"(af[mi][3]),
                                   "r"(bfm[ni][0]), "r"(bfm[ni][1]));
        }
    };

    load_stage(0, 0);
    load_stage(1, 1);
#pragma unroll 1
    for (int kt = 0; kt < KT; kt++) {
        if (kt < KT - 1) asm volatile("cp.async.wait_group 1;");
        else             asm volatile("cp.async.wait_group 0;");
        __syncthreads();                       // reads of buf (kt+2)%3 (iter kt-1) done chip-wide
        if (kt + 2 < KT) load_stage(kt + 2, (kt + 2) % NSTAGE);
        compute(kt % NSTAGE);
    }

    // ---- counting epilogue (pads pre-masked; no bounds check) ----
    const int m_base = m0 + wm * 32;
    const int n_base = n0 + wn * 64;
    const int r_in = lane >> 2;
    const int c_in = (lane & 3) * 2;
    const int wb = n_base >> 5;

#pragma unroll
    for (int mi = 0; mi < 2; mi++) {
        int r0 = m_base + mi * 16 + r_in;
        int r1 = r0 + 8;
        float t0 = g_targets[r0], t1 = g_targets[r1];
        unsigned k00 = ~g_mask[(size_t)r0 * NW + wb];
        unsigned k01 = ~g_mask[(size_t)r0 * NW + wb + 1];
        unsigned k10 = ~g_mask[(size_t)r1 * NW + wb];
        unsigned k11 = ~g_mask[(size_t)r1 * NW + wb + 1];
        int c0 = 0, c1 = 0;
#pragma unroll
        for (int ni = 0; ni < 8; ni++) {
#pragma unroll
            for (int e = 0; e < 2; e++) {
                int p = ni * 8 + c_in + e;
                unsigned kw0 = (p < 32) ? k00 : k01;
                unsigned kw1 = (p < 32) ? k10 : k11;
                c0 += (int)((kw0 >> (p & 31)) & 1u) & (int)(acc[mi][ni][e]     >= t0);
                c1 += (int)((kw1 >> (p & 31)) & 1u) & (int)(acc[mi][ni][2 + e] >= t1);
            }
        }
        c0 += __shfl_xor_sync(0xffffffffu, c0, 1);
        c0 += __shfl_xor_sync(0xffffffffu, c0, 2);
        c1 += __shfl_xor_sync(0xffffffffu, c1, 1);
        c1 += __shfl_xor_sync(0xffffffffu, c1, 2);
        if ((lane & 3) == 0) {
            atomicAdd(&g_counts[r0], c0);
            atomicAdd(&g_counts[r1], c1);
        }
    }
}

// ---------------- [4] finalize ----------------
__global__ void k_final(float* __restrict__ out) {
    int i = blockIdx.x * 256 + threadIdx.x;
    if (i < B_ROWS) out[i] = 1.0f + (float)g_counts[i];
}

// ---------------- launch ----------------
extern "C" void kernel_launch(void* const* d_in, const int* in_sizes, int n_in,
                              void* d_out, int out_size) {
    const float* q   = (const float*)d_in[0];
    const float* rhs = (const float*)d_in[1];
    const void*  queries = d_in[2];
    const void*  filt    = d_in[3];
    float* out = (float*)d_out;

    cudaFuncSetAttribute(k_gemm, cudaFuncAttributeMaxDynamicSharedMemorySize, SMEM_DYN);

    k_prep0<<<(B_ROWS * NW) / 256, 256>>>(q, (const unsigned*)queries);
    k_prep_rhsT<<<dim3(NPAD / 32, D_DIM / 32), dim3(32, 8)>>>(rhs);
    k_row<<<B_ROWS, 128>>>(q, rhs, queries, filt);
    k_gemm<<<dim3(B_ROWS / BM, NPAD / BN), 256, SMEM_DYN>>>();
    k_final<<<(B_ROWS + 255) / 256, 256>>>(out);
}